// round 4
// baseline (speedup 1.0000x reference)
#include <cuda_runtime.h>
#include <cstdint>

// ---------------- problem constants ----------------
#define NUM_SPARSE   26
#define NCHUNK       28           // user + item + 26 sparse, K=64 each
#define TILE_B       128
#define STAGES       3
#define SPARSE_VOCAB 100000
#define THREADS      288          // 8 consumer warps + 1 producer warp

// padded rows: 64 f32 + 4 pad = 68 f32 = 272B (bank-rotation, conflict-free ldmatrix)
#define ROWF 68
#define ROWB 272
#define A_TILE_BYTES (TILE_B * ROWB)     // 34816
#define W_TILE_BYTES (128 * ROWB)        // 34816
#define TX_BYTES     (TILE_B * 256 + W_TILE_BYTES)   // 32768 + 34816

// smem offsets (from 256-aligned base)
#define OFF_A    0
#define OFF_W    (STAGES * A_TILE_BYTES)                  // 104448
#define OFF_IDS  (OFF_W + STAGES * W_TILE_BYTES)          // 208896
#define OFF_B1   (OFF_IDS + NCHUNK * TILE_B * 4)          // +14336 = 223232
#define OFF_W2   (OFF_B1 + 512)
#define OFF_PART (OFF_W2 + 512)                           // 256 f32
#define OFF_MBAR (OFF_PART + 1024)                        // 6 x 8B
#define SMEM_USED (OFF_MBAR + 64)
#define SMEM_DYN  (SMEM_USED + 256)

// W1 transposed scratch: [chunk][n=128][68 f32]
__device__ __align__(256) float g_Wt[NCHUNK * 128 * ROWF];

// ---------------- helpers ----------------
__device__ __forceinline__ uint32_t smem_u32(const void* p) {
    uint32_t a;
    asm("{ .reg .u64 t; cvta.to.shared.u64 t, %1; cvt.u32.u64 %0, t; }" : "=r"(a) : "l"(p));
    return a;
}
__device__ __forceinline__ void mbar_init(uint32_t m, uint32_t cnt) {
    asm volatile("mbarrier.init.shared.b64 [%0], %1;" :: "r"(m), "r"(cnt) : "memory");
}
__device__ __forceinline__ void mbar_expect_tx(uint32_t m, uint32_t bytes) {
    asm volatile("mbarrier.arrive.expect_tx.shared.b64 _, [%0], %1;" :: "r"(m), "r"(bytes) : "memory");
}
__device__ __forceinline__ void mbar_arrive(uint32_t m) {
    asm volatile("mbarrier.arrive.shared.b64 _, [%0];" :: "r"(m) : "memory");
}
__device__ __forceinline__ void mbar_wait(uint32_t m, uint32_t parity) {
    asm volatile(
        "{\n\t.reg .pred P;\n\t"
        "W%=:\n\t"
        "mbarrier.try_wait.parity.acquire.cta.shared::cta.b64 P, [%0], %1, 0x989680;\n\t"
        "@!P bra W%=;\n\t}"
        :: "r"(m), "r"(parity) : "memory");
}
__device__ __forceinline__ void bulk_g2s(uint32_t dst, const void* src, uint32_t bytes,
                                         uint32_t mbar) {
    asm volatile(
        "cp.async.bulk.shared::cluster.global.mbarrier::complete_tx::bytes [%0], [%1], %2, [%3];"
        :: "r"(dst), "l"(src), "r"(bytes), "r"(mbar) : "memory");
}
__device__ __forceinline__ void ldm4(uint32_t* r, uint32_t addr) {
    asm volatile("ldmatrix.sync.aligned.m8n8.x4.shared.b16 {%0,%1,%2,%3}, [%4];"
                 : "=r"(r[0]), "=r"(r[1]), "=r"(r[2]), "=r"(r[3]) : "r"(addr));
}
__device__ __forceinline__ void mma_tf32(float* c, const uint32_t* a, const uint32_t* b) {
    asm volatile(
        "mma.sync.aligned.m16n8k8.row.col.f32.tf32.tf32.f32 "
        "{%0,%1,%2,%3}, {%4,%5,%6,%7}, {%8,%9}, {%0,%1,%2,%3};\n"
        : "+f"(c[0]), "+f"(c[1]), "+f"(c[2]), "+f"(c[3])
        : "r"(a[0]), "r"(a[1]), "r"(a[2]), "r"(a[3]), "r"(b[0]), "r"(b[1]));
}

// ---------------- W1 transpose pre-kernel ----------------
__global__ void w1_transpose_kernel(const float* __restrict__ W1) {
    const int i = blockIdx.x * blockDim.x + threadIdx.x;   // over 1792*128
    if (i >= 1792 * 128) return;
    const int k = i >> 7;          // 0..1791
    const int n = i & 127;
    const int f = k >> 6;          // chunk
    const int kk = k & 63;
    g_Wt[(f * 128 + n) * ROWF + kk] = W1[i];
}

// ---------------- main fused kernel ----------------
__global__ void __launch_bounds__(THREADS, 1)
dlrm_fused2(const int* __restrict__ user_ids,
            const int* __restrict__ item_ids,
            const int* __restrict__ sparse_features,
            const float* __restrict__ user_emb,
            const float* __restrict__ item_emb,
            const float* __restrict__ sparse_tables,
            const float* __restrict__ b1g,
            const float* __restrict__ w2g,
            const float* __restrict__ b2g,
            float* __restrict__ out)
{
    extern __shared__ char smem_raw[];
    char* base = (char*)(((uintptr_t)smem_raw + 255) & ~(uintptr_t)255);
    const uint32_t sb   = smem_u32(base);
    const uint32_t a0   = sb + OFF_A;
    const uint32_t w0   = sb + OFF_W;
    int*   ids  = (int*)(base + OFF_IDS);
    float* b1s  = (float*)(base + OFF_B1);
    float* w2s  = (float*)(base + OFF_W2);
    float* part = (float*)(base + OFF_PART);
    const uint32_t mb_full  = sb + OFF_MBAR;        // 3 x 8B
    const uint32_t mb_empty = mb_full + 24;         // 3 x 8B

    const int tid  = threadIdx.x;
    const int wid  = tid >> 5;
    const int lane = tid & 31;
    const int row0 = blockIdx.x * TILE_B;

    if (tid == 0) {
        #pragma unroll
        for (int s = 0; s < STAGES; s++) {
            mbar_init(mb_full + s * 8, 1);    // 1 expect_tx arrival + tx bytes
            mbar_init(mb_empty + s * 8, 8);   // 8 consumer warps
        }
    }
    // stage ids / b1 / w2
    for (int i = tid; i < NCHUNK * TILE_B; i += THREADS) {
        const int f = i >> 7;
        const int r = i & 127;
        int v;
        if (f == 0)      v = user_ids[row0 + r];
        else if (f == 1) v = item_ids[row0 + r];
        else             v = sparse_features[(size_t)(row0 + r) * NUM_SPARSE + (f - 2)];
        ids[f * TILE_B + r] = v;
    }
    if (tid < 128) { b1s[tid] = b1g[tid]; w2s[tid] = w2g[tid]; }
    __syncthreads();

    if (wid == 8) {
        // ================= producer warp =================
        int s = 0;
        uint32_t par = 1;    // fresh-barrier wait passes with parity 1
        for (int f = 0; f < NCHUNK; f++) {
            mbar_wait(mb_empty + s * 8, par);
            const uint32_t fullb = mb_full + s * 8;
            if (lane == 0) {
                mbar_expect_tx(fullb, TX_BYTES);
                bulk_g2s(w0 + s * W_TILE_BYTES, g_Wt + (size_t)f * 128 * ROWF,
                         W_TILE_BYTES, fullb);
            }
            const float* tbl = (f == 0) ? user_emb
                             : (f == 1) ? item_emb
                             : sparse_tables + (size_t)(f - 2) * SPARSE_VOCAB * 64;
            const uint32_t aS = a0 + s * A_TILE_BYTES;
            #pragma unroll
            for (int i = 0; i < 4; i++) {
                const int r = lane + 32 * i;
                const int idx = ids[f * TILE_B + r];
                bulk_g2s(aS + r * ROWB, tbl + (size_t)idx * 64, 256, fullb);
            }
            if (++s == STAGES) { s = 0; par ^= 1; }
        }
    } else {
        // ================= 8 consumer warps =================
        const int wm = (wid & 3) * 32;     // M offset (batch rows)
        const int wn = (wid >> 2) * 64;    // N offset (hidden cols)
        const int g   = lane >> 2;
        const int tig = lane & 3;

        // ldmatrix lane address components
        const uint32_t aRow   = wm + (lane & 15);
        const uint32_t aCol16 = (lane >> 4) * 16;
        const uint32_t bRow   = wn + (lane & 7) + ((lane >> 4) << 3);
        const uint32_t bCol16 = ((lane >> 3) & 1) * 16;

        float acc[2][8][4];
        #pragma unroll
        for (int mt = 0; mt < 2; mt++)
            #pragma unroll
            for (int nt = 0; nt < 8; nt++)
                #pragma unroll
                for (int i = 0; i < 4; i++) acc[mt][nt][i] = 0.0f;

        int s = 0;
        uint32_t par = 0;
        for (int f = 0; f < NCHUNK; f++) {
            mbar_wait(mb_full + s * 8, par);
            const uint32_t aBase = a0 + s * A_TILE_BYTES + aRow * ROWB + aCol16;
            const uint32_t bBase = w0 + s * W_TILE_BYTES + bRow * ROWB + bCol16;

            #pragma unroll
            for (int ks = 0; ks < 8; ks++) {
                uint32_t aa[2][4];
                uint32_t bb[4][4];
                ldm4(aa[0], aBase + ks * 32);
                ldm4(aa[1], aBase + 16 * ROWB + ks * 32);
                #pragma unroll
                for (int q = 0; q < 4; q++)
                    ldm4(bb[q], bBase + q * 16 * ROWB + ks * 32);
                #pragma unroll
                for (int mt = 0; mt < 2; mt++)
                    #pragma unroll
                    for (int q = 0; q < 4; q++) {
                        mma_tf32(acc[mt][q * 2 + 0], aa[mt], &bb[q][0]);
                        mma_tf32(acc[mt][q * 2 + 1], aa[mt], &bb[q][2]);
                    }
            }
            if (lane == 0) mbar_arrive(mb_empty + s * 8);
            if (++s == STAGES) { s = 0; par ^= 1; }
        }

        // epilogue: bias + relu + dot(W2) partials
        #pragma unroll
        for (int mt = 0; mt < 2; mt++) {
            float p0 = 0.0f, p1 = 0.0f;
            #pragma unroll
            for (int nt = 0; nt < 8; nt++) {
                const int col = wn + nt * 8 + 2 * tig;
                const float b1a = b1s[col], b1b = b1s[col + 1];
                const float w2a = w2s[col], w2b = w2s[col + 1];
                p0 += fmaxf(acc[mt][nt][0] + b1a, 0.0f) * w2a
                    + fmaxf(acc[mt][nt][1] + b1b, 0.0f) * w2b;
                p1 += fmaxf(acc[mt][nt][2] + b1a, 0.0f) * w2a
                    + fmaxf(acc[mt][nt][3] + b1b, 0.0f) * w2b;
            }
            p0 += __shfl_xor_sync(0xffffffffu, p0, 1);
            p0 += __shfl_xor_sync(0xffffffffu, p0, 2);
            p1 += __shfl_xor_sync(0xffffffffu, p1, 1);
            p1 += __shfl_xor_sync(0xffffffffu, p1, 2);
            if (tig == 0) {
                const int half = wid >> 2;
                part[half * 128 + wm + mt * 16 + g]     = p0;
                part[half * 128 + wm + mt * 16 + g + 8] = p1;
            }
        }
    }
    __syncthreads();

    if (tid < TILE_B) {
        const float raw = part[tid] + part[128 + tid] + b2g[0];
        out[row0 + tid] = 1.0f / (1.0f + __expf(-raw));
    }
}

// ---------------- host ----------------
extern "C" void kernel_launch(void* const* d_in, const int* in_sizes, int n_in,
                              void* d_out, int out_size)
{
    const int*   user_ids        = (const int*)d_in[0];
    const int*   item_ids        = (const int*)d_in[1];
    const int*   sparse_features = (const int*)d_in[2];
    const float* user_emb        = (const float*)d_in[3];
    const float* item_emb        = (const float*)d_in[4];
    const float* sparse_tables   = (const float*)d_in[5];
    const float* W1              = (const float*)d_in[6];
    const float* b1              = (const float*)d_in[7];
    const float* W2              = (const float*)d_in[8];
    const float* b2              = (const float*)d_in[9];
    float*       out             = (float*)d_out;

    // pre-transpose W1 into chunk-blocked padded scratch
    w1_transpose_kernel<<<(1792 * 128 + 255) / 256, 256>>>(W1);

    cudaFuncSetAttribute(dlrm_fused2,
                         cudaFuncAttributeMaxDynamicSharedMemorySize, SMEM_DYN);
    dlrm_fused2<<<16384 / TILE_B, THREADS, SMEM_DYN>>>(
        user_ids, item_ids, sparse_features,
        user_emb, item_emb, sparse_tables,
        b1, W2, b2, out);
}

// round 6
// speedup vs baseline: 2.7054x; 2.7054x over previous
#include <cuda_runtime.h>
#include <cstdint>

// ---------------- problem constants ----------------
#define NUM_SPARSE   26
#define NCHUNK       28           // user + item + 26 sparse, K=64 each
#define TILE_B       128
#define STAGES       3
#define SPARSE_VOCAB 100000
#define THREADS      576          // 16 consumer warps + 2 producer warps

// padded rows: 64 f32 + 4 pad = 68 f32 = 272B (bank-rotation, conflict-free ldmatrix)
#define ROWF 68
#define ROWB 272
#define A_TILE_BYTES (TILE_B * ROWB)     // 34816
#define W_TILE_BYTES (128 * ROWB)        // 34816

// smem offsets (from 256-aligned base)
#define OFF_A    0
#define OFF_W    (STAGES * A_TILE_BYTES)                  // 104448
#define OFF_IDS  (OFF_W + STAGES * W_TILE_BYTES)          // 208896
#define OFF_B1   (OFF_IDS + NCHUNK * TILE_B * 4)          // 223232
#define OFF_W2   (OFF_B1 + 512)                           // 223744
#define OFF_PART (OFF_W2 + 512)                           // 224256 (512 f32)
#define OFF_MBAR (OFF_PART + 2048)                        // 226304 (6 x 8B)
#define SMEM_USED (OFF_MBAR + 64)
#define SMEM_DYN  (SMEM_USED + 256)                       // 226624

// W1 transposed scratch: [chunk][n=128][68 f32]
__device__ __align__(256) float g_Wt[NCHUNK * 128 * ROWF];

// ---------------- helpers ----------------
__device__ __forceinline__ uint32_t smem_u32(const void* p) {
    uint32_t a;
    asm("{ .reg .u64 t; cvta.to.shared.u64 t, %1; cvt.u32.u64 %0, t; }" : "=r"(a) : "l"(p));
    return a;
}
__device__ __forceinline__ void mbar_init(uint32_t m, uint32_t cnt) {
    asm volatile("mbarrier.init.shared.b64 [%0], %1;" :: "r"(m), "r"(cnt) : "memory");
}
__device__ __forceinline__ void mbar_expect_tx(uint32_t m, uint32_t bytes) {
    asm volatile("mbarrier.arrive.expect_tx.shared.b64 _, [%0], %1;" :: "r"(m), "r"(bytes) : "memory");
}
__device__ __forceinline__ void mbar_arrive(uint32_t m) {
    asm volatile("mbarrier.arrive.shared.b64 _, [%0];" :: "r"(m) : "memory");
}
__device__ __forceinline__ void mbar_wait(uint32_t m, uint32_t parity) {
    asm volatile(
        "{\n\t.reg .pred P;\n\t"
        "W%=:\n\t"
        "mbarrier.try_wait.parity.acquire.cta.shared::cta.b64 P, [%0], %1, 0x989680;\n\t"
        "@!P bra W%=;\n\t}"
        :: "r"(m), "r"(parity) : "memory");
}
__device__ __forceinline__ void bulk_g2s(uint32_t dst, const void* src, uint32_t bytes,
                                         uint32_t mbar) {
    asm volatile(
        "cp.async.bulk.shared::cluster.global.mbarrier::complete_tx::bytes [%0], [%1], %2, [%3];"
        :: "r"(dst), "l"(src), "r"(bytes), "r"(mbar) : "memory");
}
__device__ __forceinline__ void cp16(uint32_t dst, const float* src) {
    asm volatile("cp.async.cg.shared.global [%0], [%1], 16;" :: "r"(dst), "l"(src) : "memory");
}
__device__ __forceinline__ void cpasync_mbar_arrive_noinc(uint32_t mbar) {
    asm volatile("cp.async.mbarrier.arrive.noinc.shared.b64 [%0];" :: "r"(mbar) : "memory");
}
__device__ __forceinline__ void ldm4(uint32_t* r, uint32_t addr) {
    asm volatile("ldmatrix.sync.aligned.m8n8.x4.shared.b16 {%0,%1,%2,%3}, [%4];"
                 : "=r"(r[0]), "=r"(r[1]), "=r"(r[2]), "=r"(r[3]) : "r"(addr));
}
__device__ __forceinline__ void mma_tf32(float* c, const uint32_t* a, const uint32_t* b) {
    asm volatile(
        "mma.sync.aligned.m16n8k8.row.col.f32.tf32.tf32.f32 "
        "{%0,%1,%2,%3}, {%4,%5,%6,%7}, {%8,%9}, {%0,%1,%2,%3};\n"
        : "+f"(c[0]), "+f"(c[1]), "+f"(c[2]), "+f"(c[3])
        : "r"(a[0]), "r"(a[1]), "r"(a[2]), "r"(a[3]), "r"(b[0]), "r"(b[1]));
}

// ---------------- W1 transpose pre-kernel ----------------
__global__ void w1_transpose_kernel(const float* __restrict__ W1) {
    const int i = blockIdx.x * blockDim.x + threadIdx.x;   // over 1792*128
    if (i >= 1792 * 128) return;
    const int k = i >> 7;          // 0..1791
    const int n = i & 127;
    const int f = k >> 6;          // chunk
    const int kk = k & 63;
    g_Wt[(f * 128 + n) * ROWF + kk] = W1[i];
}

// ---------------- main fused kernel ----------------
__global__ void __launch_bounds__(THREADS, 1)
dlrm_fused3(const int* __restrict__ user_ids,
            const int* __restrict__ item_ids,
            const int* __restrict__ sparse_features,
            const float* __restrict__ user_emb,
            const float* __restrict__ item_emb,
            const float* __restrict__ sparse_tables,
            const float* __restrict__ b1g,
            const float* __restrict__ w2g,
            const float* __restrict__ b2g,
            float* __restrict__ out)
{
    extern __shared__ char smem_raw[];
    char* base = (char*)(((uintptr_t)smem_raw + 255) & ~(uintptr_t)255);
    const uint32_t sb   = smem_u32(base);
    const uint32_t a0   = sb + OFF_A;
    const uint32_t w0   = sb + OFF_W;
    int*   ids  = (int*)(base + OFF_IDS);
    float* b1s  = (float*)(base + OFF_B1);
    float* w2s  = (float*)(base + OFF_W2);
    float* part = (float*)(base + OFF_PART);
    const uint32_t mb_full  = sb + OFF_MBAR;        // 3 x 8B
    const uint32_t mb_empty = mb_full + 24;         // 3 x 8B

    const int tid  = threadIdx.x;
    const int wid  = tid >> 5;
    const int lane = tid & 31;
    const int row0 = blockIdx.x * TILE_B;

    if (tid == 0) {
        #pragma unroll
        for (int s = 0; s < STAGES; s++) {
            // full: 64 producer-lane cp.async arrivals (noinc) + 1 expect_tx arrival (W bulk)
            mbar_init(mb_full + s * 8, 65);
            // empty: 16 consumer warps
            mbar_init(mb_empty + s * 8, 16);
        }
    }
    // stage ids / b1 / w2
    for (int i = tid; i < NCHUNK * TILE_B; i += THREADS) {
        const int f = i >> 7;
        const int r = i & 127;
        int v;
        if (f == 0)      v = user_ids[row0 + r];
        else if (f == 1) v = item_ids[row0 + r];
        else             v = sparse_features[(size_t)(row0 + r) * NUM_SPARSE + (f - 2)];
        ids[f * TILE_B + r] = v;
    }
    if (tid < 128) { b1s[tid] = b1g[tid]; w2s[tid] = w2g[tid]; }
    __syncthreads();

    if (wid >= 16) {
        // ================= 2 producer warps =================
        const int plane = tid - 512;        // 0..63
        int s = 0;
        uint32_t par = 1;                   // fresh-barrier wait passes with parity 1
        for (int f = 0; f < NCHUNK; f++) {
            mbar_wait(mb_empty + s * 8, par);
            const uint32_t fullb = mb_full + s * 8;
            if (plane == 0) {
                mbar_expect_tx(fullb, W_TILE_BYTES);
                bulk_g2s(w0 + s * W_TILE_BYTES, g_Wt + (size_t)f * 128 * ROWF,
                         W_TILE_BYTES, fullb);
            }
            const float* tbl = (f == 0) ? user_emb
                             : (f == 1) ? item_emb
                             : sparse_tables + (size_t)(f - 2) * SPARSE_VOCAB * 64;
            const uint32_t aS = a0 + s * A_TILE_BYTES;
            // 2048 x 16B ops over 64 lanes = 32 per lane; 16 segments per 256B row
            #pragma unroll 4
            for (int i = 0; i < 32; i++) {
                const int opid = i * 64 + plane;
                const int row  = opid >> 4;
                const int seg  = opid & 15;
                const int idx  = ids[f * TILE_B + row];
                cp16(aS + row * ROWB + seg * 16, tbl + (size_t)idx * 64 + seg * 4);
            }
            cpasync_mbar_arrive_noinc(fullb);
            if (++s == STAGES) { s = 0; par ^= 1; }
        }
    } else {
        // ================= 16 consumer warps: 32x32 tiles =================
        const int wm = (wid & 3) * 32;      // M offset (batch rows)
        const int wn = (wid >> 2) * 32;     // N offset (hidden cols)
        const int g   = lane >> 2;
        const int tig = lane & 3;

        const uint32_t aRow   = wm + (lane & 15);
        const uint32_t aCol16 = (lane >> 4) * 16;
        const uint32_t bRow   = wn + (lane & 7) + ((lane >> 4) << 3);
        const uint32_t bCol16 = ((lane >> 3) & 1) * 16;

        float acc[2][4][4];
        #pragma unroll
        for (int mt = 0; mt < 2; mt++)
            #pragma unroll
            for (int nt = 0; nt < 4; nt++)
                #pragma unroll
                for (int i = 0; i < 4; i++) acc[mt][nt][i] = 0.0f;

        int s = 0;
        uint32_t par = 0;
        for (int f = 0; f < NCHUNK; f++) {
            mbar_wait(mb_full + s * 8, par);
            const uint32_t aBase = a0 + s * A_TILE_BYTES + aRow * ROWB + aCol16;
            const uint32_t bBase = w0 + s * W_TILE_BYTES + bRow * ROWB + bCol16;

            #pragma unroll
            for (int ks = 0; ks < 8; ks++) {
                uint32_t aa[2][4];
                uint32_t bb[2][4];
                ldm4(aa[0], aBase + ks * 32);
                ldm4(aa[1], aBase + 16 * ROWB + ks * 32);
                #pragma unroll
                for (int q = 0; q < 2; q++)
                    ldm4(bb[q], bBase + q * 16 * ROWB + ks * 32);
                #pragma unroll
                for (int mt = 0; mt < 2; mt++)
                    #pragma unroll
                    for (int q = 0; q < 2; q++) {
                        mma_tf32(acc[mt][q * 2 + 0], aa[mt], &bb[q][0]);
                        mma_tf32(acc[mt][q * 2 + 1], aa[mt], &bb[q][2]);
                    }
            }
            if (lane == 0) mbar_arrive(mb_empty + s * 8);
            if (++s == STAGES) { s = 0; par ^= 1; }
        }

        // epilogue: bias + relu + dot(W2) partials over this warp's 32 cols
        #pragma unroll
        for (int mt = 0; mt < 2; mt++) {
            float p0 = 0.0f, p1 = 0.0f;
            #pragma unroll
            for (int nt = 0; nt < 4; nt++) {
                const int col = wn + nt * 8 + 2 * tig;
                const float b1a = b1s[col], b1b = b1s[col + 1];
                const float w2a = w2s[col], w2b = w2s[col + 1];
                p0 += fmaxf(acc[mt][nt][0] + b1a, 0.0f) * w2a
                    + fmaxf(acc[mt][nt][1] + b1b, 0.0f) * w2b;
                p1 += fmaxf(acc[mt][nt][2] + b1a, 0.0f) * w2a
                    + fmaxf(acc[mt][nt][3] + b1b, 0.0f) * w2b;
            }
            p0 += __shfl_xor_sync(0xffffffffu, p0, 1);
            p0 += __shfl_xor_sync(0xffffffffu, p0, 2);
            p1 += __shfl_xor_sync(0xffffffffu, p1, 1);
            p1 += __shfl_xor_sync(0xffffffffu, p1, 2);
            if (tig == 0) {
                const int grp = wid >> 2;            // column quarter
                part[grp * 128 + wm + mt * 16 + g]     = p0;
                part[grp * 128 + wm + mt * 16 + g + 8] = p1;
            }
        }
    }
    __syncthreads();

    if (tid < TILE_B) {
        const float raw = part[tid] + part[128 + tid] + part[256 + tid] + part[384 + tid]
                        + b2g[0];
        out[row0 + tid] = 1.0f / (1.0f + __expf(-raw));
    }
}

// ---------------- host ----------------
extern "C" void kernel_launch(void* const* d_in, const int* in_sizes, int n_in,
                              void* d_out, int out_size)
{
    const int*   user_ids        = (const int*)d_in[0];
    const int*   item_ids        = (const int*)d_in[1];
    const int*   sparse_features = (const int*)d_in[2];
    const float* user_emb        = (const float*)d_in[3];
    const float* item_emb        = (const float*)d_in[4];
    const float* sparse_tables   = (const float*)d_in[5];
    const float* W1              = (const float*)d_in[6];
    const float* b1              = (const float*)d_in[7];
    const float* W2              = (const float*)d_in[8];
    const float* b2              = (const float*)d_in[9];
    float*       out             = (float*)d_out;

    // pre-transpose W1 into chunk-blocked padded scratch
    w1_transpose_kernel<<<(1792 * 128 + 255) / 256, 256>>>(W1);

    cudaFuncSetAttribute(dlrm_fused3,
                         cudaFuncAttributeMaxDynamicSharedMemorySize, SMEM_DYN);
    dlrm_fused3<<<16384 / TILE_B, THREADS, SMEM_DYN>>>(
        user_ids, item_ids, sparse_features,
        user_emb, item_emb, sparse_tables,
        b1, W2, b2, out);
}